// round 2
// baseline (speedup 1.0000x reference)
#include <cuda_runtime.h>
#include <cstdint>

#define B_      128
#define P_      8732
#define C_      21
#define N_      16
#define CHUNK   256
#define NCHUNK  ((P_ + CHUNK - 1) / CHUNK)   // 35

// ---------------- scratch (no allocs allowed) ----------------
__device__ unsigned long long g_best[B_ * N_];   // per (b,obj): (iou_bits<<32)|(0xFFFFFFFF-p)
__device__ float  g_bestv[B_ * P_];              // per (b,p): max iou over objects
__device__ int    g_bestn[B_ * P_];              // per (b,p): argmax object (first-tie)
__device__ float  g_conf_neg[B_ * P_];           // CE for negatives, 0 for positives
__device__ int    g_npos[B_];
__device__ double g_loc_sum;
__device__ double g_pos_ce;
__device__ double g_hard_sum;

// ---------------- kernel 0: init ----------------
__global__ void k_init() {
    int i = blockIdx.x * blockDim.x + threadIdx.x;
    if (i < B_ * N_) g_best[i] = 0ull;
    if (i < B_)      g_npos[i] = 0;
    if (i == 0) { g_loc_sum = 0.0; g_pos_ce = 0.0; g_hard_sum = 0.0; }
}

// ---------------- kernel 1: matching ----------------
// grid (NCHUNK, B_), block CHUNK. One prior per thread.
__global__ void k_match(const float* __restrict__ boxes,
                        const float* __restrict__ priors) {
    int bb  = blockIdx.y;
    int p   = blockIdx.x * CHUNK + threadIdx.x;
    bool valid = (p < P_);

    __shared__ float sb[N_][4];
    __shared__ float sarea[N_];
    __shared__ unsigned long long skey[N_];

    if (threadIdx.x < N_) {
        int n = threadIdx.x;
        const float* bp = boxes + ((size_t)bb * N_ + n) * 4;
        float x1 = bp[0], y1 = bp[1], x2 = bp[2], y2 = bp[3];
        sb[n][0] = x1; sb[n][1] = y1; sb[n][2] = x2; sb[n][3] = y2;
        sarea[n] = (x2 - x1) * (y2 - y1);
        skey[n]  = 0ull;
    }
    __syncthreads();

    float px1 = 0.f, py1 = 0.f, px2 = 0.f, py2 = 0.f, parea = 0.f;
    if (valid) {
        float4 pc = ((const float4*)priors)[p];
        px1 = pc.x - pc.z * 0.5f; py1 = pc.y - pc.w * 0.5f;
        px2 = pc.x + pc.z * 0.5f; py2 = pc.y + pc.w * 0.5f;
        parea = (px2 - px1) * (py2 - py1);
    }

    float maxv = -1e30f; int argn = 0;
    #pragma unroll
    for (int n = 0; n < N_; n++) {
        float iou = 0.0f;
        if (valid) {
            float lx = fmaxf(sb[n][0], px1);
            float ly = fmaxf(sb[n][1], py1);
            float hx = fminf(sb[n][2], px2);
            float hy = fminf(sb[n][3], py2);
            float dx = fmaxf(hx - lx, 0.0f);
            float dy = fmaxf(hy - ly, 0.0f);
            float inter = dx * dy;
            iou = inter / (sarea[n] + parea - inter);
            if (iou > maxv) { maxv = iou; argn = n; }   // first-index tie-break
        }
        // per-object argmax over all priors: pack (iou, prefer lower p on tie)
        unsigned long long key = 0ull;
        if (valid)
            key = (((unsigned long long)__float_as_uint(iou)) << 32) |
                  (unsigned long long)(0xFFFFFFFFu - (unsigned)p);
        #pragma unroll
        for (int off = 16; off > 0; off >>= 1) {
            unsigned long long o = __shfl_down_sync(0xffffffffu, key, off);
            if (o > key) key = o;
        }
        if ((threadIdx.x & 31) == 0) atomicMax(&skey[n], key);
    }

    if (valid) {
        size_t idx = (size_t)bb * P_ + p;
        g_bestv[idx] = maxv;
        g_bestn[idx] = argn;
    }
    __syncthreads();
    if (threadIdx.x < N_)
        atomicMax(&g_best[bb * N_ + threadIdx.x], skey[threadIdx.x]);
}

// ---------------- kernel 2: fused CE + loc loss ----------------
__device__ __forceinline__ float smooth_l1(float d) {
    float ad = fabsf(d);
    return (ad < 1.0f) ? 0.5f * d * d : ad - 0.5f;
}

// grid (NCHUNK, B_), block CHUNK.
__global__ void k_loss(const float* __restrict__ locs,
                       const float* __restrict__ scores,
                       const float* __restrict__ boxes,
                       const int*   __restrict__ labels,
                       const float* __restrict__ priors) {
    int bb  = blockIdx.y;
    int p0  = blockIdx.x * CHUNK;
    int tid = threadIdx.x;

    __shared__ float s_sc[CHUNK * C_];      // staged scores chunk
    __shared__ float sb[N_][4];
    __shared__ int   slab[N_];
    __shared__ int   sforce[N_];
    __shared__ float r_loc[8], r_ce[8];
    __shared__ int   r_np[8];

    if (tid < N_) {
        const float* bp = boxes + ((size_t)bb * N_ + tid) * 4;
        sb[tid][0] = bp[0]; sb[tid][1] = bp[1]; sb[tid][2] = bp[2]; sb[tid][3] = bp[3];
        slab[tid] = labels[bb * N_ + tid];
        sforce[tid] = (int)(0xFFFFFFFFu -
                            (unsigned)(g_best[bb * N_ + tid] & 0xFFFFFFFFull));
    }

    int np  = min(CHUNK, P_ - p0);
    int nf4 = (np * C_) / 4;                 // np*21 divisible by 4 (np=256 or 28)
    const float4* src = (const float4*)(scores + ((size_t)bb * P_ + p0) * C_);
    float4* dst = (float4*)s_sc;
    for (int i = tid; i < nf4; i += CHUNK) dst[i] = src[i];
    __syncthreads();

    float my_loc = 0.0f, my_ce = 0.0f; int my_np = 0;
    if (tid < np) {
        int p = p0 + tid;
        size_t idx = (size_t)bb * P_ + p;
        float maxv = g_bestv[idx];
        int   argn = g_bestn[idx];
        #pragma unroll
        for (int n = 0; n < N_; n++)          // ascending: last write wins
            if (sforce[n] == p) { argn = n; maxv = 2.0f; }
        int lab = (maxv < 0.5f) ? 0 : slab[argn];

        const float* row = s_sc + tid * C_;
        float m = row[0];
        #pragma unroll
        for (int c = 1; c < C_; c++) m = fmaxf(m, row[c]);
        float s = 0.0f;
        #pragma unroll
        for (int c = 0; c < C_; c++) s += expf(row[c] - m);
        float ce = m + logf(s) - row[lab];

        float cneg = ce;
        if (lab != 0) {
            cneg = 0.0f; my_np = 1; my_ce = ce;
            float4 pl = ((const float4*)locs)[idx];
            float4 pr = ((const float4*)priors)[p];
            float bx1 = sb[argn][0], by1 = sb[argn][1];
            float bx2 = sb[argn][2], by2 = sb[argn][3];
            float cx = (bx1 + bx2) * 0.5f, cy = (by1 + by2) * 0.5f;
            float w  = bx2 - bx1,          h  = by2 - by1;
            float t0 = (cx - pr.x) / (pr.z / 10.0f);
            float t1 = (cy - pr.y) / (pr.w / 10.0f);
            float t2 = logf(w / pr.z) * 5.0f;
            float t3 = logf(h / pr.w) * 5.0f;
            my_loc = smooth_l1(pl.x - t0) + smooth_l1(pl.y - t1) +
                     smooth_l1(pl.z - t2) + smooth_l1(pl.w - t3);
        }
        g_conf_neg[idx] = cneg;
    }

    // block reduce (loc, ce, npos)
    #pragma unroll
    for (int off = 16; off > 0; off >>= 1) {
        my_loc += __shfl_down_sync(0xffffffffu, my_loc, off);
        my_ce  += __shfl_down_sync(0xffffffffu, my_ce,  off);
        my_np  += __shfl_down_sync(0xffffffffu, my_np,  off);
    }
    int w = tid >> 5;
    if ((tid & 31) == 0) { r_loc[w] = my_loc; r_ce[w] = my_ce; r_np[w] = my_np; }
    __syncthreads();
    if (tid == 0) {
        float tl = 0.f, tc = 0.f; int tn = 0;
        #pragma unroll
        for (int i = 0; i < 8; i++) { tl += r_loc[i]; tc += r_ce[i]; tn += r_np[i]; }
        if (tn) atomicAdd(&g_npos[bb], tn);
        if (tl != 0.f) atomicAdd(&g_loc_sum, (double)tl);
        if (tc != 0.f) atomicAdd(&g_pos_ce, (double)tc);
    }
}

// ---------------- kernel 3: per-batch top-k sum ----------------
// grid B_, block 256. Bit binary-search on f32 bit pattern (values >= 0).
__global__ void k_topk() {
    int bb  = blockIdx.x;
    int tid = threadIdx.x;
    __shared__ float sv[P_];
    __shared__ int   rcnt[8];
    __shared__ float rsum[8];
    __shared__ int   s_total;

    for (int i = tid; i < P_; i += 256)
        sv[i] = g_conf_neg[(size_t)bb * P_ + i];
    __syncthreads();

    int k = 3 * g_npos[bb];
    if (k <= 0) return;                       // uniform branch per block

    unsigned prefix = 0u;
    for (int bit = 30; bit >= 0; bit--) {
        unsigned cand = prefix | (1u << bit);
        int c = 0;
        for (int i = tid; i < P_; i += 256)
            c += (__float_as_uint(sv[i]) >= cand);
        #pragma unroll
        for (int off = 16; off > 0; off >>= 1)
            c += __shfl_down_sync(0xffffffffu, c, off);
        if ((tid & 31) == 0) rcnt[tid >> 5] = c;
        __syncthreads();
        if (tid == 0) {
            int t = 0;
            #pragma unroll
            for (int i = 0; i < 8; i++) t += rcnt[i];
            s_total = t;
        }
        __syncthreads();
        if (s_total >= k) prefix = cand;
        __syncthreads();
    }

    float kth = __uint_as_float(prefix);
    int cgt = 0; float sgt = 0.0f;
    for (int i = tid; i < P_; i += 256) {
        float v = sv[i];
        if (v > kth) { cgt++; sgt += v; }
    }
    #pragma unroll
    for (int off = 16; off > 0; off >>= 1) {
        cgt += __shfl_down_sync(0xffffffffu, cgt, off);
        sgt += __shfl_down_sync(0xffffffffu, sgt, off);
    }
    if ((tid & 31) == 0) { rcnt[tid >> 5] = cgt; rsum[tid >> 5] = sgt; }
    __syncthreads();
    if (tid == 0) {
        int tc = 0; float ts = 0.f;
        #pragma unroll
        for (int i = 0; i < 8; i++) { tc += rcnt[i]; ts += rsum[i]; }
        double hard = (double)ts + (double)(k - tc) * (double)kth;
        atomicAdd(&g_hard_sum, hard);
    }
}

// ---------------- kernel 4: finalize ----------------
__global__ void k_final(float* __restrict__ out) {
    int npt = 0;
    for (int b = 0; b < B_; b++) npt += g_npos[b];
    double nd = (double)npt;
    double conf = (g_hard_sum + g_pos_ce) / nd;
    double loc  = g_loc_sum / (nd * 4.0);
    out[0] = (float)(conf + loc);
}

// ---------------- launch ----------------
extern "C" void kernel_launch(void* const* d_in, const int* in_sizes, int n_in,
                              void* d_out, int out_size) {
    const float* locs   = (const float*)d_in[0];
    const float* scores = (const float*)d_in[1];
    const float* boxes  = (const float*)d_in[2];
    const int*   labels = (const int*)  d_in[3];
    const float* priors = (const float*)d_in[4];
    float* out = (float*)d_out;

    k_init<<<(B_ * N_ + 255) / 256, 256>>>();
    dim3 grid(NCHUNK, B_);
    k_match<<<grid, CHUNK>>>(boxes, priors);
    k_loss<<<grid, CHUNK>>>(locs, scores, boxes, labels, priors);
    k_topk<<<B_, 256>>>();
    k_final<<<1, 1>>>(out);
}

// round 3
// speedup vs baseline: 1.1563x; 1.1563x over previous
#include <cuda_runtime.h>
#include <cstdint>

#define B_      128
#define P_      8732
#define C_      21
#define N_      16
#define CHUNK   256
#define NCHUNK  ((P_ + CHUNK - 1) / CHUNK)   // 35

// ---------------- scratch (no allocs allowed) ----------------
__device__ unsigned long long g_best[B_ * N_];   // per (b,obj): (iou_bits<<32)|(0xFFFFFFFF-p)
__device__ float  g_conf_neg[B_ * P_];           // CE for negatives, 0 for positives
__device__ int    g_npos[B_];
__device__ double g_loc_sum;
__device__ double g_pos_ce;
__device__ double g_hard_sum;

__device__ __forceinline__ float iou_fn(float bx1, float by1, float bx2, float by2,
                                        float barea,
                                        float px1, float py1, float px2, float py2,
                                        float parea) {
    float lx = fmaxf(bx1, px1), ly = fmaxf(by1, py1);
    float hx = fminf(bx2, px2), hy = fminf(by2, py2);
    float dx = fmaxf(hx - lx, 0.0f), dy = fmaxf(hy - ly, 0.0f);
    float inter = dx * dy;
    return __fdividef(inter, barea + parea - inter);
}

// ---------------- kernel 1: per-object best prior (+ init) ----------------
// grid B_, block 1024. One block owns one batch -> plain writes, no init kernel.
__global__ void __launch_bounds__(1024, 1)
k_objbest(const float* __restrict__ boxes, const float* __restrict__ priors) {
    int bb  = blockIdx.x;
    int tid = threadIdx.x;

    __shared__ float sb[N_][4];
    __shared__ float sarea[N_];
    __shared__ unsigned long long skey[N_];

    if (bb == 0 && tid == 0) { g_loc_sum = 0.0; g_pos_ce = 0.0; g_hard_sum = 0.0; }
    if (tid == 0) g_npos[bb] = 0;
    if (tid < N_) {
        const float* bp = boxes + ((size_t)bb * N_ + tid) * 4;
        float x1 = bp[0], y1 = bp[1], x2 = bp[2], y2 = bp[3];
        sb[tid][0] = x1; sb[tid][1] = y1; sb[tid][2] = x2; sb[tid][3] = y2;
        sarea[tid] = (x2 - x1) * (y2 - y1);
        skey[tid]  = 0ull;
    }
    __syncthreads();

    unsigned long long keys[N_];
    #pragma unroll
    for (int n = 0; n < N_; n++) keys[n] = 0ull;

    for (int p = tid; p < P_; p += 1024) {
        float4 pc = ((const float4*)priors)[p];
        float px1 = pc.x - pc.z * 0.5f, py1 = pc.y - pc.w * 0.5f;
        float px2 = pc.x + pc.z * 0.5f, py2 = pc.y + pc.w * 0.5f;
        float parea = (px2 - px1) * (py2 - py1);
        #pragma unroll
        for (int n = 0; n < N_; n++) {
            float iou = iou_fn(sb[n][0], sb[n][1], sb[n][2], sb[n][3], sarea[n],
                               px1, py1, px2, py2, parea);
            unsigned long long key =
                (((unsigned long long)__float_as_uint(iou)) << 32) |
                (unsigned long long)(0xFFFFFFFFu - (unsigned)p);
            if (key > keys[n]) keys[n] = key;
        }
    }

    #pragma unroll
    for (int n = 0; n < N_; n++) {
        unsigned long long k = keys[n];
        #pragma unroll
        for (int off = 16; off > 0; off >>= 1) {
            unsigned long long o = __shfl_down_sync(0xffffffffu, k, off);
            if (o > k) k = o;
        }
        if ((tid & 31) == 0) atomicMax(&skey[n], k);
    }
    __syncthreads();
    if (tid < N_) g_best[bb * N_ + tid] = skey[tid];
}

// ---------------- kernel 2: fused match + CE + loc loss ----------------
__device__ __forceinline__ float smooth_l1(float d) {
    float ad = fabsf(d);
    return (ad < 1.0f) ? 0.5f * d * d : ad - 0.5f;
}

// grid (NCHUNK, B_), block CHUNK.
__global__ void k_loss(const float* __restrict__ locs,
                       const float* __restrict__ scores,
                       const float* __restrict__ boxes,
                       const int*   __restrict__ labels,
                       const float* __restrict__ priors) {
    int bb  = blockIdx.y;
    int p0  = blockIdx.x * CHUNK;
    int tid = threadIdx.x;

    __shared__ float s_sc[CHUNK * C_];      // staged scores chunk
    __shared__ float sb[N_][4];
    __shared__ float sarea[N_];
    __shared__ int   slab[N_];
    __shared__ int   sforce[N_];
    __shared__ float r_loc[8], r_ce[8];
    __shared__ int   r_np[8];

    if (tid < N_) {
        const float* bp = boxes + ((size_t)bb * N_ + tid) * 4;
        float x1 = bp[0], y1 = bp[1], x2 = bp[2], y2 = bp[3];
        sb[tid][0] = x1; sb[tid][1] = y1; sb[tid][2] = x2; sb[tid][3] = y2;
        sarea[tid] = (x2 - x1) * (y2 - y1);
        slab[tid] = labels[bb * N_ + tid];
        sforce[tid] = (int)(0xFFFFFFFFu -
                            (unsigned)(g_best[bb * N_ + tid] & 0xFFFFFFFFull));
    }

    int np  = min(CHUNK, P_ - p0);
    int nf4 = (np * C_) / 4;                 // np*21 divisible by 4 (np=256 or 28)
    const float4* src = (const float4*)(scores + ((size_t)bb * P_ + p0) * C_);
    float4* dst = (float4*)s_sc;
    for (int i = tid; i < nf4; i += CHUNK) dst[i] = src[i];
    __syncthreads();

    float my_loc = 0.0f, my_ce = 0.0f; int my_np = 0;
    if (tid < np) {
        int p = p0 + tid;
        size_t idx = (size_t)bb * P_ + p;

        float4 pr = ((const float4*)priors)[p];
        float px1 = pr.x - pr.z * 0.5f, py1 = pr.y - pr.w * 0.5f;
        float px2 = pr.x + pr.z * 0.5f, py2 = pr.y + pr.w * 0.5f;
        float parea = (px2 - px1) * (py2 - py1);

        float maxv = -1e30f; int argn = 0;
        #pragma unroll
        for (int n = 0; n < N_; n++) {
            float iou = iou_fn(sb[n][0], sb[n][1], sb[n][2], sb[n][3], sarea[n],
                               px1, py1, px2, py2, parea);
            if (iou > maxv) { maxv = iou; argn = n; }   // first-index tie-break
        }
        #pragma unroll
        for (int n = 0; n < N_; n++)          // ascending: last write wins
            if (sforce[n] == p) { argn = n; maxv = 2.0f; }
        int lab = (maxv < 0.5f) ? 0 : slab[argn];

        const float* row = s_sc + tid * C_;
        float m = row[0];
        #pragma unroll
        for (int c = 1; c < C_; c++) m = fmaxf(m, row[c]);
        float s = 0.0f;
        #pragma unroll
        for (int c = 0; c < C_; c++) s += expf(row[c] - m);
        float ce = m + logf(s) - row[lab];

        float cneg = ce;
        if (lab != 0) {
            cneg = 0.0f; my_np = 1; my_ce = ce;
            float4 pl = ((const float4*)locs)[idx];
            float bx1 = sb[argn][0], by1 = sb[argn][1];
            float bx2 = sb[argn][2], by2 = sb[argn][3];
            float cx = (bx1 + bx2) * 0.5f, cy = (by1 + by2) * 0.5f;
            float w  = bx2 - bx1,          h  = by2 - by1;
            float t0 = (cx - pr.x) / (pr.z / 10.0f);
            float t1 = (cy - pr.y) / (pr.w / 10.0f);
            float t2 = logf(w / pr.z) * 5.0f;
            float t3 = logf(h / pr.w) * 5.0f;
            my_loc = smooth_l1(pl.x - t0) + smooth_l1(pl.y - t1) +
                     smooth_l1(pl.z - t2) + smooth_l1(pl.w - t3);
        }
        g_conf_neg[idx] = cneg;
    }

    // block reduce (loc, ce, npos)
    #pragma unroll
    for (int off = 16; off > 0; off >>= 1) {
        my_loc += __shfl_down_sync(0xffffffffu, my_loc, off);
        my_ce  += __shfl_down_sync(0xffffffffu, my_ce,  off);
        my_np  += __shfl_down_sync(0xffffffffu, my_np,  off);
    }
    int w = tid >> 5;
    if ((tid & 31) == 0) { r_loc[w] = my_loc; r_ce[w] = my_ce; r_np[w] = my_np; }
    __syncthreads();
    if (tid == 0) {
        float tl = 0.f, tc = 0.f; int tn = 0;
        #pragma unroll
        for (int i = 0; i < 8; i++) { tl += r_loc[i]; tc += r_ce[i]; tn += r_np[i]; }
        if (tn) atomicAdd(&g_npos[bb], tn);
        if (tl != 0.f) atomicAdd(&g_loc_sum, (double)tl);
        if (tc != 0.f) atomicAdd(&g_pos_ce, (double)tc);
    }
}

// ---------------- kernel 3: per-batch top-k sum (radix select) ----------------
// grid B_, block 1024. 4 passes of 256-bin histograms on f32 bit pattern (v >= 0).
__global__ void __launch_bounds__(1024, 1)
k_topk() {
    int bb  = blockIdx.x;
    int tid = threadIdx.x;
    int lane = tid & 31, wid = tid >> 5;

    __shared__ unsigned svu[P_];
    __shared__ unsigned hist[8][256];
    __shared__ int      s_byte;
    __shared__ unsigned s_gt;
    __shared__ float    rsum[32];
    __shared__ unsigned rcnt[32];

    for (int i = tid; i < P_; i += 1024)
        svu[i] = __float_as_uint(g_conf_neg[(size_t)bb * P_ + i]);
    __syncthreads();

    int k = 3 * g_npos[bb];
    if (k <= 0) return;

    unsigned prefix = 0u;
    int kr = k;
    #pragma unroll
    for (int pass = 0; pass < 4; pass++) {
        int shift = 24 - 8 * pass;
        unsigned* hflat = &hist[0][0];
        for (int i = tid; i < 8 * 256; i += 1024) hflat[i] = 0u;
        __syncthreads();

        for (int i = tid; i < P_; i += 1024) {
            unsigned u = svu[i];
            bool match = (pass == 0) || ((u >> (shift + 8)) == prefix);
            if (match) atomicAdd(&hist[wid & 7][(u >> shift) & 255], 1u);
        }
        __syncthreads();

        if (tid < 256) {
            unsigned s = 0;
            #pragma unroll
            for (int h = 0; h < 8; h++) s += hist[h][tid];
            hist[0][tid] = s;
        }
        __syncthreads();

        if (tid < 32) {
            // lane l owns bytes 255-8l .. 248-8l (descending)
            unsigned vals[8]; unsigned lsum = 0;
            #pragma unroll
            for (int j = 0; j < 8; j++) {
                vals[j] = hist[0][255 - (lane * 8 + j)];
                lsum += vals[j];
            }
            // inclusive scan of lsum across lanes -> exclusive prefix
            unsigned incl = lsum;
            #pragma unroll
            for (int off = 1; off < 32; off <<= 1) {
                unsigned o = __shfl_up_sync(0xffffffffu, incl, off);
                if (lane >= off) incl += o;
            }
            unsigned pre = incl - lsum;
            int found = -1; unsigned gt = 0; unsigned cum = pre;
            #pragma unroll
            for (int j = 0; j < 8; j++) {
                if (found < 0 && cum + vals[j] >= (unsigned)kr) { found = j; gt = cum; }
                cum += vals[j];
            }
            unsigned mask = __ballot_sync(0xffffffffu, found >= 0);
            if (mask) {
                int leader = __ffs(mask) - 1;
                if (lane == leader) { s_byte = 255 - (lane * 8 + found); s_gt = gt; }
            } else if (lane == 0) { s_byte = 0; s_gt = 0; }
        }
        __syncthreads();
        prefix = (prefix << 8) | (unsigned)s_byte;
        kr -= (int)s_gt;
        __syncthreads();
    }

    unsigned kth_bits = prefix;
    float kth = __uint_as_float(kth_bits);

    unsigned cgt = 0; float sgt = 0.0f;
    for (int i = tid; i < P_; i += 1024) {
        unsigned u = svu[i];
        if (u > kth_bits) { cgt++; sgt += __uint_as_float(u); }
    }
    #pragma unroll
    for (int off = 16; off > 0; off >>= 1) {
        cgt += __shfl_down_sync(0xffffffffu, cgt, off);
        sgt += __shfl_down_sync(0xffffffffu, sgt, off);
    }
    if (lane == 0) { rcnt[wid] = cgt; rsum[wid] = sgt; }
    __syncthreads();
    if (tid == 0) {
        unsigned tc = 0; float ts = 0.f;
        #pragma unroll
        for (int i = 0; i < 32; i++) { tc += rcnt[i]; ts += rsum[i]; }
        double hard = (double)ts + (double)(k - (int)tc) * (double)kth;
        atomicAdd(&g_hard_sum, hard);
    }
}

// ---------------- kernel 4: finalize ----------------
__global__ void k_final(float* __restrict__ out) {
    int tid = threadIdx.x;            // 128 threads
    int np = g_npos[tid];
    #pragma unroll
    for (int off = 16; off > 0; off >>= 1)
        np += __shfl_down_sync(0xffffffffu, np, off);
    __shared__ int r[4];
    if ((tid & 31) == 0) r[tid >> 5] = np;
    __syncthreads();
    if (tid == 0) {
        int npt = r[0] + r[1] + r[2] + r[3];
        double nd = (double)npt;
        double conf = (g_hard_sum + g_pos_ce) / nd;
        double loc  = g_loc_sum / (nd * 4.0);
        out[0] = (float)(conf + loc);
    }
}

// ---------------- launch ----------------
extern "C" void kernel_launch(void* const* d_in, const int* in_sizes, int n_in,
                              void* d_out, int out_size) {
    const float* locs   = (const float*)d_in[0];
    const float* scores = (const float*)d_in[1];
    const float* boxes  = (const float*)d_in[2];
    const int*   labels = (const int*)  d_in[3];
    const float* priors = (const float*)d_in[4];
    float* out = (float*)d_out;

    k_objbest<<<B_, 1024>>>(boxes, priors);
    dim3 grid(NCHUNK, B_);
    k_loss<<<grid, CHUNK>>>(locs, scores, boxes, labels, priors);
    k_topk<<<B_, 1024>>>();
    k_final<<<1, 128>>>(out);
}

// round 4
// speedup vs baseline: 1.2655x; 1.0944x over previous
#include <cuda_runtime.h>
#include <cstdint>

#define B_    128
#define P_    8732
#define C_    21
#define N_    16
#define TPB   1024
#define NCH   ((P_ + TPB - 1) / TPB)   // 9
#define PPAD  8736                      // P_ padded to /16

// dynamic smem layout (bytes):
//   s_conf  : PPAD floats        34944
//   s_bestv : PPAD floats        34944
//   s_bestn : PPAD uchar          8736
//   s_sc    : TPB*C_ floats      86016   (reused as hist[8][256] in phase C)
#define SMEM_BYTES (PPAD*4 + PPAD*4 + PPAD + TPB*C_*4)

// ---------------- per-batch partials (plain stores, deterministic) ----------
__device__ double g_pl[B_];   // loc sum
__device__ double g_pc[B_];   // positive CE sum
__device__ double g_ph[B_];   // hard-neg sum
__device__ int    g_pn[B_];   // n_pos
__device__ int    g_done;     // ticket; reset by last block

__device__ __forceinline__ float smooth_l1(float d) {
    float ad = fabsf(d);
    return (ad < 1.0f) ? 0.5f * d * d : ad - 0.5f;
}

__global__ void __launch_bounds__(TPB, 1)
k_all(const float* __restrict__ locs,   const float* __restrict__ scores,
      const float* __restrict__ boxes,  const int*   __restrict__ labels,
      const float* __restrict__ priors, float* __restrict__ out) {
    extern __shared__ char smem_raw[];
    float*         s_conf  = (float*)smem_raw;
    float*         s_bestv = s_conf + PPAD;
    unsigned char* s_bestn = (unsigned char*)(s_bestv + PPAD);
    float*         s_sc    = (float*)(s_bestn + PPAD);
    unsigned*      hist    = (unsigned*)s_sc;          // reuse in phase C

    __shared__ float4 sbx[N_];      // x1,y1,x2,y2
    __shared__ float  sarea[N_];
    __shared__ float4 sccwh[N_];    // cx,cy,w,h
    __shared__ int    slab[N_];
    __shared__ int    sforce[N_];
    __shared__ unsigned long long skey[N_];
    __shared__ float  rf[32], rf2[32];
    __shared__ int    ri[32];
    __shared__ int    s_np, s_byte, s_last;
    __shared__ unsigned s_gt;
    __shared__ double rdl[32], rdc[32], rdh[32];
    __shared__ int    rdn[32];

    int bb = blockIdx.x, tid = threadIdx.x;
    int lane = tid & 31, wid = tid >> 5;

    if (tid < N_) {
        const float* bp = boxes + ((size_t)bb * N_ + tid) * 4;
        float x1 = bp[0], y1 = bp[1], x2 = bp[2], y2 = bp[3];
        sbx[tid]   = make_float4(x1, y1, x2, y2);
        sarea[tid] = (x2 - x1) * (y2 - y1);
        sccwh[tid] = make_float4((x1 + x2) * 0.5f, (y1 + y2) * 0.5f,
                                 x2 - x1, y2 - y1);
        slab[tid]  = labels[bb * N_ + tid];
        skey[tid]  = 0ull;
    }
    __syncthreads();

    // ---------------- Phase A: all IoUs once ----------------
    float bv[N_]; int bpp[N_];
    #pragma unroll
    for (int n = 0; n < N_; n++) { bv[n] = -1.0f; bpp[n] = 0; }

    for (int p = tid; p < P_; p += TPB) {
        float4 pc = ((const float4*)priors)[p];
        float px1 = pc.x - pc.z * 0.5f, py1 = pc.y - pc.w * 0.5f;
        float px2 = pc.x + pc.z * 0.5f, py2 = pc.y + pc.w * 0.5f;
        float parea = (px2 - px1) * (py2 - py1);
        float maxv = -1e30f; int argn = 0;
        #pragma unroll
        for (int n = 0; n < N_; n++) {
            float4 b = sbx[n];
            float lx = fmaxf(b.x, px1), ly = fmaxf(b.y, py1);
            float hx = fminf(b.z, px2), hy = fminf(b.w, py2);
            float dx = fmaxf(hx - lx, 0.0f), dy = fmaxf(hy - ly, 0.0f);
            float inter = dx * dy;
            float iou = __fdividef(inter, sarea[n] + parea - inter);
            if (iou > maxv) { maxv = iou; argn = n; }   // first-index tie-break
            if (iou > bv[n]) { bv[n] = iou; bpp[n] = p; } // ascending p: first wins
        }
        s_bestv[p] = maxv;
        s_bestn[p] = (unsigned char)argn;
    }

    #pragma unroll
    for (int n = 0; n < N_; n++) {
        unsigned long long k =
            (((unsigned long long)__float_as_uint(bv[n])) << 32) |
            (unsigned long long)(0xFFFFFFFFu - (unsigned)bpp[n]);
        #pragma unroll
        for (int off = 16; off > 0; off >>= 1) {
            unsigned long long o = __shfl_down_sync(0xffffffffu, k, off);
            if (o > k) k = o;
        }
        if (lane == 0) atomicMax(&skey[n], k);
    }
    __syncthreads();
    if (tid < N_)
        sforce[tid] = (int)(0xFFFFFFFFu - (unsigned)(skey[tid] & 0xFFFFFFFFull));
    __syncthreads();

    // ---------------- Phase B: CE + loc loss, conf_neg -> smem ----------------
    float my_loc = 0.0f, my_ce = 0.0f; int my_np = 0;
    for (int c = 0; c < NCH; c++) {
        int p0 = c * TPB;
        int np = min(TPB, P_ - p0);
        int nf4 = (np * C_) >> 2;                    // np*21 divisible by 4
        const float4* src = (const float4*)(scores + ((size_t)bb * P_ + p0) * C_);
        float4* dst = (float4*)s_sc;
        for (int i = tid; i < nf4; i += TPB) dst[i] = src[i];
        __syncthreads();

        if (tid < np) {
            int p = p0 + tid;
            float maxv = s_bestv[p];
            int   argn = s_bestn[p];
            #pragma unroll
            for (int n = 0; n < N_; n++)             // ascending: last write wins
                if (sforce[n] == p) { argn = n; maxv = 2.0f; }
            int lab = (maxv < 0.5f) ? 0 : slab[argn];

            const float* row = s_sc + tid * C_;
            float m = row[0];
            #pragma unroll
            for (int cc = 1; cc < C_; cc++) m = fmaxf(m, row[cc]);
            float s = 0.0f;
            #pragma unroll
            for (int cc = 0; cc < C_; cc++) s += __expf(row[cc] - m);
            float ce = m + __logf(s) - row[lab];

            float cneg = ce;
            if (lab != 0) {
                cneg = 0.0f; my_np++; my_ce += ce;
                float4 pl = ((const float4*)locs)[(size_t)bb * P_ + p];
                float4 pr = ((const float4*)priors)[p];
                float4 g  = sccwh[argn];
                float t0 = (g.x - pr.x) / (pr.z * 0.1f);
                float t1 = (g.y - pr.y) / (pr.w * 0.1f);
                float t2 = __logf(__fdividef(g.z, pr.z)) * 5.0f;
                float t3 = __logf(__fdividef(g.w, pr.w)) * 5.0f;
                my_loc += smooth_l1(pl.x - t0) + smooth_l1(pl.y - t1) +
                          smooth_l1(pl.z - t2) + smooth_l1(pl.w - t3);
            }
            s_conf[p] = cneg;
        }
        __syncthreads();                             // s_sc reuse next chunk
    }

    // block reduce loc/ce/npos
    #pragma unroll
    for (int off = 16; off > 0; off >>= 1) {
        my_loc += __shfl_down_sync(0xffffffffu, my_loc, off);
        my_ce  += __shfl_down_sync(0xffffffffu, my_ce,  off);
        my_np  += __shfl_down_sync(0xffffffffu, my_np,  off);
    }
    if (lane == 0) { rf[wid] = my_loc; rf2[wid] = my_ce; ri[wid] = my_np; }
    __syncthreads();
    if (tid == 0) {
        float tl = 0.f, tc = 0.f; int tn = 0;
        #pragma unroll
        for (int i = 0; i < 32; i++) { tl += rf[i]; tc += rf2[i]; tn += ri[i]; }
        g_pl[bb] = (double)tl;
        g_pc[bb] = (double)tc;
        g_pn[bb] = tn;
        s_np = tn;
    }
    __syncthreads();

    // ---------------- Phase C: top-k radix select on smem ----------------
    int k = 3 * s_np;
    double hard = 0.0;
    if (k > 0) {
        unsigned prefix = 0u; int kr = k;
        #pragma unroll
        for (int pass = 0; pass < 4; pass++) {
            int shift = 24 - 8 * pass;
            for (int i = tid; i < 8 * 256; i += TPB) hist[i] = 0u;
            __syncthreads();
            for (int i = tid; i < P_; i += TPB) {
                unsigned u = __float_as_uint(s_conf[i]);
                bool match = (pass == 0) || ((u >> (shift + 8)) == prefix);
                if (match) atomicAdd(&hist[(wid & 7) * 256 + ((u >> shift) & 255)], 1u);
            }
            __syncthreads();
            if (tid < 256) {
                unsigned s = 0;
                #pragma unroll
                for (int h = 0; h < 8; h++) s += hist[h * 256 + tid];
                __syncthreads();          // all reads done before overwrite
                hist[tid] = s;
            } else __syncthreads();
            __syncthreads();
            if (tid < 32) {
                unsigned vals[8]; unsigned lsum = 0;
                #pragma unroll
                for (int j = 0; j < 8; j++) {
                    vals[j] = hist[255 - (lane * 8 + j)];
                    lsum += vals[j];
                }
                unsigned incl = lsum;
                #pragma unroll
                for (int off = 1; off < 32; off <<= 1) {
                    unsigned o = __shfl_up_sync(0xffffffffu, incl, off);
                    if (lane >= off) incl += o;
                }
                unsigned pre = incl - lsum;
                int found = -1; unsigned gt = 0; unsigned cum = pre;
                #pragma unroll
                for (int j = 0; j < 8; j++) {
                    if (found < 0 && cum + vals[j] >= (unsigned)kr) { found = j; gt = cum; }
                    cum += vals[j];
                }
                unsigned mask = __ballot_sync(0xffffffffu, found >= 0);
                if (mask) {
                    int leader = __ffs(mask) - 1;
                    if (lane == leader) { s_byte = 255 - (lane * 8 + found); s_gt = gt; }
                } else if (lane == 0) { s_byte = 0; s_gt = 0; }
            }
            __syncthreads();
            prefix = (prefix << 8) | (unsigned)s_byte;
            kr -= (int)s_gt;
            __syncthreads();
        }

        unsigned kb = prefix;
        float kth = __uint_as_float(kb);
        unsigned cgt = 0; float sgt = 0.0f;
        for (int i = tid; i < P_; i += TPB) {
            float v = s_conf[i];
            if (__float_as_uint(v) > kb) { cgt++; sgt += v; }
        }
        #pragma unroll
        for (int off = 16; off > 0; off >>= 1) {
            cgt += __shfl_down_sync(0xffffffffu, cgt, off);
            sgt += __shfl_down_sync(0xffffffffu, sgt, off);
        }
        if (lane == 0) { ri[wid] = (int)cgt; rf[wid] = sgt; }
        __syncthreads();
        if (tid == 0) {
            int tc = 0; float ts = 0.f;
            #pragma unroll
            for (int i = 0; i < 32; i++) { tc += ri[i]; ts += rf[i]; }
            hard = (double)ts + (double)(k - tc) * (double)kth;
        }
    }
    if (tid == 0) g_ph[bb] = hard;

    // ---------------- ticket + finalize by last block ----------------
    __threadfence();
    if (tid == 0) {
        int t = atomicAdd(&g_done, 1);
        s_last = (t == B_ - 1);
    }
    __syncthreads();
    if (s_last) {
        __threadfence();
        double l = 0.0, ce = 0.0, h = 0.0; int n = 0;
        if (tid < B_) { l = g_pl[tid]; ce = g_pc[tid]; h = g_ph[tid]; n = g_pn[tid]; }
        #pragma unroll
        for (int off = 16; off > 0; off >>= 1) {
            l  += __shfl_down_sync(0xffffffffu, l,  off);
            ce += __shfl_down_sync(0xffffffffu, ce, off);
            h  += __shfl_down_sync(0xffffffffu, h,  off);
            n  += __shfl_down_sync(0xffffffffu, n,  off);
        }
        if (lane == 0) { rdl[wid] = l; rdc[wid] = ce; rdh[wid] = h; rdn[wid] = n; }
        __syncthreads();
        if (tid == 0) {
            double tl = 0.0, tc = 0.0, th = 0.0; int tn = 0;
            #pragma unroll
            for (int i = 0; i < 32; i++) {
                tl += rdl[i]; tc += rdc[i]; th += rdh[i]; tn += rdn[i];
            }
            double nd = (double)tn;
            out[0] = (float)((th + tc) / nd + tl / (nd * 4.0));
            g_done = 0;                               // reset for next replay
        }
    }
}

// ---------------- launch ----------------
extern "C" void kernel_launch(void* const* d_in, const int* in_sizes, int n_in,
                              void* d_out, int out_size) {
    const float* locs   = (const float*)d_in[0];
    const float* scores = (const float*)d_in[1];
    const float* boxes  = (const float*)d_in[2];
    const int*   labels = (const int*)  d_in[3];
    const float* priors = (const float*)d_in[4];
    float* out = (float*)d_out;

    cudaFuncSetAttribute(k_all, cudaFuncAttributeMaxDynamicSharedMemorySize,
                         SMEM_BYTES);
    k_all<<<B_, TPB, SMEM_BYTES>>>(locs, scores, boxes, labels, priors, out);
}

// round 5
// speedup vs baseline: 1.3531x; 1.0692x over previous
#include <cuda_runtime.h>
#include <cstdint>

#define B_     128
#define P_     8732
#define C_     21
#define N_     16
#define TPB    1024
#define CH     512
#define NCHUNK ((P_ + CH - 1) / CH)     // 18 (17 full + 28)
#define PPAD   8736
#define BUF_F4 ((CH * C_) / 4)          // 2688 float4 per buffer

// dynamic smem: s_conf(34944) + s_bestv(34944) + s_bestn(8736) + 2 bufs(86016)
#define SMEM_BYTES (PPAD*4 + PPAD*4 + PPAD + 2*CH*C_*4)

// ---------------- per-batch partials (plain stores, deterministic) ----------
__device__ double g_pl[B_];
__device__ double g_pc[B_];
__device__ double g_ph[B_];
__device__ int    g_pn[B_];
__device__ int    g_done;

__device__ __forceinline__ float smooth_l1(float d) {
    float ad = fabsf(d);
    return (ad < 1.0f) ? 0.5f * d * d : ad - 0.5f;
}

__device__ __forceinline__ void stage_chunk(float4* dst, const float4* src,
                                            int nf4, int tid) {
    for (int i = tid; i < nf4; i += TPB) {
        unsigned d = (unsigned)__cvta_generic_to_shared(dst + i);
        asm volatile("cp.async.cg.shared.global [%0], [%1], 16;"
                     :: "r"(d), "l"(src + i));
    }
    asm volatile("cp.async.commit_group;");
}

__global__ void __launch_bounds__(TPB, 1)
k_all(const float* __restrict__ locs,   const float* __restrict__ scores,
      const float* __restrict__ boxes,  const int*   __restrict__ labels,
      const float* __restrict__ priors, float* __restrict__ out) {
    extern __shared__ char smem_raw[];
    float*         s_conf  = (float*)smem_raw;
    float*         s_bestv = s_conf + PPAD;
    unsigned char* s_bestn = (unsigned char*)(s_bestv + PPAD);
    float*         buf0    = (float*)(s_bestn + PPAD);
    float*         buf1    = buf0 + CH * C_;
    unsigned*      hist    = (unsigned*)buf0;       // reuse in phase C (8KB)

    __shared__ float4 sbx[N_];
    __shared__ float  sarea[N_];
    __shared__ float4 sccwh[N_];
    __shared__ int    slab[N_];
    __shared__ unsigned long long skey[N_];
    __shared__ float  rf[32], rf2[32];
    __shared__ int    ri[32];
    __shared__ int    s_np, s_byte, s_last;
    __shared__ unsigned s_gt;
    __shared__ double rdl[32], rdc[32], rdh[32];
    __shared__ int    rdn[32];

    int bb = blockIdx.x, tid = threadIdx.x;
    int lane = tid & 31, wid = tid >> 5;

    // ---- prefetch score chunks 0,1 immediately (overlap with phase A) ----
    const float4* sc4 = (const float4*)(scores + (size_t)bb * P_ * C_);
    stage_chunk((float4*)buf0, sc4,          BUF_F4, tid);
    stage_chunk((float4*)buf1, sc4 + BUF_F4, BUF_F4, tid);

    if (tid < N_) {
        const float* bp = boxes + ((size_t)bb * N_ + tid) * 4;
        float x1 = bp[0], y1 = bp[1], x2 = bp[2], y2 = bp[3];
        sbx[tid]   = make_float4(x1, y1, x2, y2);
        sarea[tid] = (x2 - x1) * (y2 - y1);
        sccwh[tid] = make_float4((x1 + x2) * 0.5f, (y1 + y2) * 0.5f,
                                 x2 - x1, y2 - y1);
        slab[tid]  = labels[bb * N_ + tid];
        skey[tid]  = 0ull;
    }
    __syncthreads();

    // ---------------- Phase A: all IoUs once ----------------
    unsigned long long keys[N_];
    #pragma unroll
    for (int n = 0; n < N_; n++) keys[n] = 0ull;

    for (int p = tid; p < P_; p += TPB) {
        float4 pc = ((const float4*)priors)[p];
        float px1 = pc.x - pc.z * 0.5f, py1 = pc.y - pc.w * 0.5f;
        float px2 = pc.x + pc.z * 0.5f, py2 = pc.y + pc.w * 0.5f;
        float parea = (px2 - px1) * (py2 - py1);
        float maxv = -1e30f; int argn = 0;
        unsigned long long lowp = (unsigned long long)(0xFFFFFFFFu - (unsigned)p);
        #pragma unroll
        for (int n = 0; n < N_; n++) {
            float4 b = sbx[n];
            float lx = fmaxf(b.x, px1), ly = fmaxf(b.y, py1);
            float hx = fminf(b.z, px2), hy = fminf(b.w, py2);
            float dx = fmaxf(hx - lx, 0.0f), dy = fmaxf(hy - ly, 0.0f);
            float inter = dx * dy;
            float iou = __fdividef(inter, sarea[n] + parea - inter);
            if (iou > maxv) { maxv = iou; argn = n; }      // first-index tie-break
            unsigned long long key =
                (((unsigned long long)__float_as_uint(iou)) << 32) | lowp;
            if (key > keys[n]) keys[n] = key;              // lower p wins ties
        }
        s_bestv[p] = maxv;
        s_bestn[p] = (unsigned char)argn;
    }

    #pragma unroll
    for (int n = 0; n < N_; n++) {
        unsigned long long k = keys[n];
        #pragma unroll
        for (int off = 16; off > 0; off >>= 1) {
            unsigned long long o = __shfl_down_sync(0xffffffffu, k, off);
            if (o > k) k = o;
        }
        if (lane == 0) atomicMax(&skey[n], k);
    }
    __syncthreads();
    if (tid == 0) {
        // forced-prior override, ascending n = last write wins (matches ref)
        #pragma unroll
        for (int n = 0; n < N_; n++) {
            int p = (int)(0xFFFFFFFFu - (unsigned)(skey[n] & 0xFFFFFFFFull));
            s_bestv[p] = 2.0f;
            s_bestn[p] = (unsigned char)n;
        }
    }
    __syncthreads();

    // ---------------- Phase B: pipelined CE + loc loss ----------------
    float my_loc = 0.0f, my_ce = 0.0f; int my_np = 0;
    for (int c = 0; c < NCHUNK; c++) {
        if (c + 1 < NCHUNK) asm volatile("cp.async.wait_group 1;");
        else                asm volatile("cp.async.wait_group 0;");
        __syncthreads();

        float* buf = (c & 1) ? buf1 : buf0;
        int p0 = c * CH;
        int np = min(CH, P_ - p0);

        if (tid < np) {
            int p = p0 + tid;
            float maxv = s_bestv[p];
            int   argn = s_bestn[p];
            int lab = (maxv < 0.5f) ? 0 : slab[argn];

            const float* row = buf + tid * C_;
            float m = row[0];
            #pragma unroll
            for (int cc = 1; cc < C_; cc++) m = fmaxf(m, row[cc]);
            float s = 0.0f;
            #pragma unroll
            for (int cc = 0; cc < C_; cc++) s += __expf(row[cc] - m);
            float ce = m + __logf(s) - row[lab];

            float cneg = ce;
            if (lab != 0) {
                cneg = 0.0f; my_np++; my_ce += ce;
                float4 pl = ((const float4*)locs)[(size_t)bb * P_ + p];
                float4 pr = ((const float4*)priors)[p];
                float4 g  = sccwh[argn];
                float t0 = (g.x - pr.x) / (pr.z * 0.1f);
                float t1 = (g.y - pr.y) / (pr.w * 0.1f);
                float t2 = __logf(__fdividef(g.z, pr.z)) * 5.0f;
                float t3 = __logf(__fdividef(g.w, pr.w)) * 5.0f;
                my_loc += smooth_l1(pl.x - t0) + smooth_l1(pl.y - t1) +
                          smooth_l1(pl.z - t2) + smooth_l1(pl.w - t3);
            }
            s_conf[p] = cneg;
        }
        __syncthreads();                 // buffer reads done before refill

        int cn = c + 2;
        if (cn < NCHUNK) {
            int nf4 = (min(CH, P_ - cn * CH) * C_) >> 2;
            stage_chunk((float4*)((c & 1) ? buf1 : buf0),
                        sc4 + cn * BUF_F4, nf4, tid);
        }
    }

    // block reduce loc/ce/npos
    #pragma unroll
    for (int off = 16; off > 0; off >>= 1) {
        my_loc += __shfl_down_sync(0xffffffffu, my_loc, off);
        my_ce  += __shfl_down_sync(0xffffffffu, my_ce,  off);
        my_np  += __shfl_down_sync(0xffffffffu, my_np,  off);
    }
    if (lane == 0) { rf[wid] = my_loc; rf2[wid] = my_ce; ri[wid] = my_np; }
    __syncthreads();
    if (tid == 0) {
        float tl = 0.f, tc = 0.f; int tn = 0;
        #pragma unroll
        for (int i = 0; i < 32; i++) { tl += rf[i]; tc += rf2[i]; tn += ri[i]; }
        g_pl[bb] = (double)tl;
        g_pc[bb] = (double)tc;
        g_pn[bb] = tn;
        s_np = tn;
    }
    __syncthreads();

    // ---------------- Phase C: top-k radix select on smem ----------------
    int k = 3 * s_np;
    double hard = 0.0;
    if (k > 0) {
        unsigned prefix = 0u; int kr = k;
        #pragma unroll
        for (int pass = 0; pass < 4; pass++) {
            int shift = 24 - 8 * pass;
            for (int i = tid; i < 8 * 256; i += TPB) hist[i] = 0u;
            __syncthreads();
            for (int i = tid; i < P_; i += TPB) {
                unsigned u = __float_as_uint(s_conf[i]);
                bool match = (pass == 0) || ((u >> (shift + 8)) == prefix);
                if (match) atomicAdd(&hist[(wid & 7) * 256 + ((u >> shift) & 255)], 1u);
            }
            __syncthreads();
            if (tid < 256) {
                unsigned s = 0;
                #pragma unroll
                for (int h = 0; h < 8; h++) s += hist[h * 256 + tid];
                __syncthreads();
                hist[tid] = s;
            } else __syncthreads();
            __syncthreads();
            if (tid < 32) {
                unsigned vals[8]; unsigned lsum = 0;
                #pragma unroll
                for (int j = 0; j < 8; j++) {
                    vals[j] = hist[255 - (lane * 8 + j)];
                    lsum += vals[j];
                }
                unsigned incl = lsum;
                #pragma unroll
                for (int off = 1; off < 32; off <<= 1) {
                    unsigned o = __shfl_up_sync(0xffffffffu, incl, off);
                    if (lane >= off) incl += o;
                }
                unsigned pre = incl - lsum;
                int found = -1; unsigned gt = 0; unsigned cum = pre;
                #pragma unroll
                for (int j = 0; j < 8; j++) {
                    if (found < 0 && cum + vals[j] >= (unsigned)kr) { found = j; gt = cum; }
                    cum += vals[j];
                }
                unsigned mask = __ballot_sync(0xffffffffu, found >= 0);
                if (mask) {
                    int leader = __ffs(mask) - 1;
                    if (lane == leader) { s_byte = 255 - (lane * 8 + found); s_gt = gt; }
                } else if (lane == 0) { s_byte = 0; s_gt = 0; }
            }
            __syncthreads();
            prefix = (prefix << 8) | (unsigned)s_byte;
            kr -= (int)s_gt;
            __syncthreads();
        }

        unsigned kb = prefix;
        float kth = __uint_as_float(kb);
        unsigned cgt = 0; float sgt = 0.0f;
        for (int i = tid; i < P_; i += TPB) {
            float v = s_conf[i];
            if (__float_as_uint(v) > kb) { cgt++; sgt += v; }
        }
        #pragma unroll
        for (int off = 16; off > 0; off >>= 1) {
            cgt += __shfl_down_sync(0xffffffffu, cgt, off);
            sgt += __shfl_down_sync(0xffffffffu, sgt, off);
        }
        if (lane == 0) { ri[wid] = (int)cgt; rf[wid] = sgt; }
        __syncthreads();
        if (tid == 0) {
            int tc = 0; float ts = 0.f;
            #pragma unroll
            for (int i = 0; i < 32; i++) { tc += ri[i]; ts += rf[i]; }
            hard = (double)ts + (double)(k - tc) * (double)kth;
        }
    }
    if (tid == 0) g_ph[bb] = hard;

    // ---------------- ticket + finalize by last block ----------------
    __threadfence();
    if (tid == 0) {
        int t = atomicAdd(&g_done, 1);
        s_last = (t == B_ - 1);
    }
    __syncthreads();
    if (s_last) {
        __threadfence();
        double l = 0.0, ce = 0.0, h = 0.0; int n = 0;
        if (tid < B_) { l = g_pl[tid]; ce = g_pc[tid]; h = g_ph[tid]; n = g_pn[tid]; }
        #pragma unroll
        for (int off = 16; off > 0; off >>= 1) {
            l  += __shfl_down_sync(0xffffffffu, l,  off);
            ce += __shfl_down_sync(0xffffffffu, ce, off);
            h  += __shfl_down_sync(0xffffffffu, h,  off);
            n  += __shfl_down_sync(0xffffffffu, n,  off);
        }
        if (lane == 0) { rdl[wid] = l; rdc[wid] = ce; rdh[wid] = h; rdn[wid] = n; }
        __syncthreads();
        if (tid == 0) {
            double tl = 0.0, tc = 0.0, th = 0.0; int tn = 0;
            #pragma unroll
            for (int i = 0; i < 32; i++) {
                tl += rdl[i]; tc += rdc[i]; th += rdh[i]; tn += rdn[i];
            }
            double nd = (double)tn;
            out[0] = (float)((th + tc) / nd + tl / (nd * 4.0));
            g_done = 0;
        }
    }
}

// ---------------- launch ----------------
extern "C" void kernel_launch(void* const* d_in, const int* in_sizes, int n_in,
                              void* d_out, int out_size) {
    const float* locs   = (const float*)d_in[0];
    const float* scores = (const float*)d_in[1];
    const float* boxes  = (const float*)d_in[2];
    const int*   labels = (const int*)  d_in[3];
    const float* priors = (const float*)d_in[4];
    float* out = (float*)d_out;

    cudaFuncSetAttribute(k_all, cudaFuncAttributeMaxDynamicSharedMemorySize,
                         SMEM_BYTES);
    k_all<<<B_, TPB, SMEM_BYTES>>>(locs, scores, boxes, labels, priors, out);
}